// round 4
// baseline (speedup 1.0000x reference)
#include <cuda_runtime.h>
#include <math.h>
#include <stdint.h>

#define B_  4
#define T_  1024
#define H_  1024
#define NH_ 32
#define D_  32
#define M_  2
#define K_  1024

// ---------------- scratch (static device globals; no allocation) ----------------
__device__ float g_qraw [B_*T_*H_];
__device__ float g_kraw [B_*T_*H_];
__device__ float g_vraw [B_*T_*H_];
__device__ float g_phiq [B_*T_*H_];   // [b,h,t,d]
__device__ float g_phik [B_*T_*H_];   // [b,h,t,d]
__device__ float g_vt   [B_*T_*H_];   // [b,h,t,d]
__device__ float g_braw [B_*T_*NH_*M_];
__device__ float g_mraw [B_*T_*NH_*M_];
__device__ float g_beta [B_*NH_*M_*T_]; // [b,h,m,t]
__device__ float g_mix  [B_*NH_*M_*T_]; // [b,h,m,t]
__device__ float g_ypart[2*B_*T_*H_];   // [m][b,t,H]
__device__ float g_ysum [B_*T_*H_];
__device__ float g_z    [B_*T_*H_];

// ==================== helpers ====================
__device__ __forceinline__ uint32_t smem_u32(const void* p) {
    uint32_t a;
    asm("{ .reg .u64 t; cvta.to.shared.u64 t, %1; cvt.u32.u64 %0, t; }" : "=r"(a) : "l"(p));
    return a;
}

__device__ __forceinline__ void cp_async16(uint32_t dst, const void* src) {
    asm volatile("cp.async.ca.shared.global [%0], [%1], 16;" :: "r"(dst), "l"(src));
}
__device__ __forceinline__ void cp_commit() { asm volatile("cp.async.commit_group;"); }
template<int N> __device__ __forceinline__ void cp_wait() {
    asm volatile("cp.async.wait_group %0;" :: "n"(N));
}

__device__ __forceinline__ uint32_t f2tf32(float x) {
    uint32_t u;
    asm("cvt.rna.tf32.f32 %0, %1;" : "=r"(u) : "f"(x));
    return u;
}

__device__ __forceinline__ void mma_tf32x(float* c, const uint32_t* a, const uint32_t* b) {
    asm volatile("mma.sync.aligned.m16n8k8.row.col.f32.tf32.tf32.f32 "
        "{%0,%1,%2,%3}, {%4,%5,%6,%7}, {%8,%9}, {%0,%1,%2,%3};"
        : "+f"(c[0]), "+f"(c[1]), "+f"(c[2]), "+f"(c[3])
        : "r"(a[0]), "r"(a[1]), "r"(a[2]), "r"(a[3]), "r"(b[0]), "r"(b[1]));
}

// ==================== tf32x3 mma.sync GEMM ====================
// C[M,N] = A[M,K] . B[N,K]^T. CTA tile 128x128, KC=32 double-buffered via cp.async.
// 8 warps: warp tile 64x32 (wm = wid/4, wn = wid%4).
// MODE 0: plain (QKV). MODE 1: beta/mix fused (B rows 0-63 Wbeta, 64-127 Wmix;
//   out cols 0-63 -> C, 64-127 -> C2, both [row][64]). MODE 2: epilogue + bias + xres.

#define S_WORDS 12
#define SLICE_FL (128*S_WORDS)       // floats per k8-slice (128 rows x 12 words)
#define BUF_FL   (4*SLICE_FL)        // 4 slices = KC 32
#define A_FL     (2*BUF_FL)
#define GSMEM_BYTES (4*BUF_FL*4)     // A(2 buf) + B(2 buf) = 98304 B

template<int MODE>
__global__ void __launch_bounds__(256) gemm_mma(
    const float* __restrict__ A, const float* __restrict__ Bw1, const float* __restrict__ Bw2,
    float* __restrict__ C, float* __restrict__ C2,
    const float* __restrict__ bias, const float* __restrict__ xres)
{
    extern __shared__ float sm[];
    float* As = sm;                 // [2 buf][4 slice][128 row][12 words]
    float* Bs = sm + A_FL;

    const int tid  = threadIdx.x;
    const int row0 = blockIdx.y * 128;
    const int col0 = blockIdx.x * 128;
    const int lane = tid & 31;
    const int wm = ((tid >> 7) & 1) * 64;   // (wid>>2)*64
    const int wn = ((tid >> 5) & 3) * 32;   // (wid&3)*32

    // cp.async sources: thread covers row=tid/2, k-half = (tid&1)*16
    const int ldrow = tid >> 1;
    const int kh    = (tid & 1) * 16;
    const float* asrc = A + (size_t)(row0 + ldrow) * K_ + kh;
    const float* bsrc;
    if (MODE == 1) bsrc = ((ldrow < 64) ? Bw1 + (size_t)ldrow * K_
                                        : Bw2 + (size_t)(ldrow - 64) * K_) + kh;
    else           bsrc = Bw1 + (size_t)(col0 + ldrow) * K_ + kh;

    const uint32_t sa = smem_u32(sm);
    uint32_t offA[4];
#pragma unroll
    for (int q = 0; q < 4; q++) {
        int k = kh + q * 4;
        int s = k >> 3, w = k & 7;
        offA[q] = (uint32_t)(((s * 128 + ldrow) * S_WORDS + w) * 4);
    }

#define ISSUE(chunk, buf) do { \
    const float* _ap = asrc + (chunk) * 32; \
    const float* _bp = bsrc + (chunk) * 32; \
    uint32_t _b = sa + (uint32_t)(buf) * (BUF_FL * 4); \
    _Pragma("unroll") \
    for (int q = 0; q < 4; q++) { \
        cp_async16(_b + offA[q], _ap + q * 4); \
        cp_async16(_b + (uint32_t)(A_FL * 4) + offA[q], _bp + q * 4); \
    } \
    cp_commit(); } while (0)

    ISSUE(0, 0);
    ISSUE(1, 1);

    float cc[64];
#pragma unroll
    for (int x = 0; x < 64; x++) cc[x] = 0.f;

#define MMALOOP(AA, BB) do { \
    _Pragma("unroll") \
    for (int mt = 0; mt < 4; mt++) \
    _Pragma("unroll") \
    for (int nt = 0; nt < 4; nt++) \
        mma_tf32x(&cc[(mt*4+nt)*4], &(AA)[mt*4], &(BB)[nt*2]); } while (0)

    for (int i = 0; i < 32; i++) {
        if (i < 30) cp_wait<1>(); else cp_wait<0>();
        __syncthreads();
        const int buf = i & 1;
        const float* Ab = As + buf * BUF_FL;
        const float* Bb = Bs + buf * BUF_FL;

        for (int s = 0; s < 4; s++) {
            const float* Asl = Ab + s * SLICE_FL;
            const float* Bsl = Bb + s * SLICE_FL;
            float af[16], bf[8];
#pragma unroll
            for (int mt = 0; mt < 4; mt++) {
                int base = (wm + mt * 16 + (lane >> 2)) * S_WORDS + (lane & 3);
                af[mt*4+0] = Asl[base];
                af[mt*4+1] = Asl[base + 8 * S_WORDS];
                af[mt*4+2] = Asl[base + 4];
                af[mt*4+3] = Asl[base + 8 * S_WORDS + 4];
            }
#pragma unroll
            for (int nt = 0; nt < 4; nt++) {
                int base = (wn + nt * 8 + (lane >> 2)) * S_WORDS + (lane & 3);
                bf[nt*2+0] = Bsl[base];
                bf[nt*2+1] = Bsl[base + 4];
            }
            uint32_t ah[16], bh[8];
#pragma unroll
            for (int x = 0; x < 16; x++) ah[x] = f2tf32(af[x]);
#pragma unroll
            for (int x = 0; x < 8;  x++) bh[x] = f2tf32(bf[x]);
            MMALOOP(ah, bh);                       // hi * hi
            {
                uint32_t al[16];
#pragma unroll
                for (int x = 0; x < 16; x++) al[x] = f2tf32(af[x] - __uint_as_float(ah[x]));
                MMALOOP(al, bh);                   // lo_a * hi_b
            }
            {
                uint32_t bl[8];
#pragma unroll
                for (int x = 0; x < 8; x++) bl[x] = f2tf32(bf[x] - __uint_as_float(bh[x]));
                MMALOOP(ah, bl);                   // hi_a * lo_b
            }
        }
        __syncthreads();
        if (i + 2 < 32) ISSUE(i + 2, buf);
    }

    // ---- epilogue ----
#pragma unroll
    for (int mt = 0; mt < 4; mt++)
#pragma unroll
    for (int nt = 0; nt < 4; nt++) {
        const int r = row0 + wm + mt * 16 + (lane >> 2);
        const int c = col0 + wn + nt * 8 + (lane & 3) * 2;
        float* p = &cc[(mt*4+nt)*4];
        if (MODE == 0) {
            *(float2*)&C[(size_t)r * H_ + c]       = make_float2(p[0], p[1]);
            *(float2*)&C[(size_t)(r+8) * H_ + c]   = make_float2(p[2], p[3]);
        } else if (MODE == 1) {
            float* d0;
            float* d1;
            if (c < 64) { d0 = &C [(size_t)r * 64 + c];      d1 = &C [(size_t)(r+8) * 64 + c]; }
            else        { d0 = &C2[(size_t)r * 64 + c - 64]; d1 = &C2[(size_t)(r+8) * 64 + c - 64]; }
            *(float2*)d0 = make_float2(p[0], p[1]);
            *(float2*)d1 = make_float2(p[2], p[3]);
        } else {
            const size_t o0 = (size_t)r * H_ + c, o1 = (size_t)(r+8) * H_ + c;
            float2 x0 = *(const float2*)&xres[o0];
            float2 x1 = *(const float2*)&xres[o1];
            float2 bb = *(const float2*)&bias[c];
            *(float2*)&C[o0] = make_float2(p[0] + bb.x + x0.x, p[1] + bb.y + x0.y);
            *(float2*)&C[o1] = make_float2(p[2] + bb.x + x1.x, p[3] + bb.y + x1.y);
        }
    }
#undef ISSUE
#undef MMALOOP
}

// ---------------- ysum = ypart[0] + ypart[1] ----------------
__global__ __launch_bounds__(256) void add_kernel(
    const float* __restrict__ a, const float* __restrict__ b, float* __restrict__ o)
{
    int i = blockIdx.x * 256 + threadIdx.x;
    float4 va = ((const float4*)a)[i];
    float4 vb = ((const float4*)b)[i];
    ((float4*)o)[i] = make_float4(va.x + vb.x, va.y + vb.y, va.z + vb.z, va.w + vb.w);
}

// ---------------- preprocess: RoPE + phi, sigmoid/clip beta, softmax mix, transpose v ----------------
__global__ __launch_bounds__(512) void prep_kernel(
    const float* __restrict__ qraw, const float* __restrict__ kraw,
    const float* __restrict__ vraw, const float* __restrict__ braw,
    const float* __restrict__ mraw, const float* __restrict__ bbeta,
    const float* __restrict__ bmix,
    float* __restrict__ phiq, float* __restrict__ phik, float* __restrict__ vt,
    float* __restrict__ beta, float* __restrict__ mixo)
{
    const int bt = blockIdx.x;           // 0..4095
    const int b  = bt >> 10;
    const int t  = bt & 1023;
    const int tid = threadIdx.x;         // 0..511
    const int h  = tid >> 4;             // 0..31
    const int i  = tid & 15;             // 0..15

    float inv = expf(-(float)i * (0.0625f * 9.210340371976184f)); // 10000^(-i/16)
    float ang = (float)t * inv;
    float s = sinf(ang), c = cosf(ang);

    size_t src = (size_t)bt * H_ + (size_t)h * 32;
    float q1 = qraw[src + i], q2 = qraw[src + 16 + i];
    float k1 = kraw[src + i], k2 = kraw[src + 16 + i];
    float rq1 = q1*c - q2*s, rq2 = q1*s + q2*c;
    float rk1 = k1*c - k2*s, rk2 = k1*s + k2*c;

    size_t dst = (((size_t)b * NH_ + h) * T_ + t) * D_;
    phiq[dst + i]      = (rq1 > 0.f) ? rq1 + 1.f : expf(rq1);
    phiq[dst + 16 + i] = (rq2 > 0.f) ? rq2 + 1.f : expf(rq2);
    phik[dst + i]      = (rk1 > 0.f) ? rk1 + 1.f : expf(rk1);
    phik[dst + 16 + i] = (rk2 > 0.f) ? rk2 + 1.f : expf(rk2);

    {
        int e  = tid * 2;
        int hh = e >> 5, dd = e & 31;
        float2 vv = *(const float2*)(vraw + (size_t)bt * H_ + e);
        size_t vd = (((size_t)b * NH_ + hh) * T_ + t) * D_ + dd;
        *(float2*)(vt + vd) = vv;
    }

    if (tid < 64) {
        float xv = braw[(size_t)bt * 64 + tid] + bbeta[tid];
        float sg = 1.f / (1.f + expf(-xv));
        sg = fminf(fmaxf(sg, 0.85f), 0.9995f);
        int hh = tid >> 1, mm = tid & 1;
        beta[(((size_t)b * NH_ + hh) * M_ + mm) * T_ + t] = sg;
    }
    if (tid < 32) {
        int hh = tid;
        float a0 = mraw[(size_t)bt * 64 + hh*2]     + bmix[hh*2];
        float a1 = mraw[(size_t)bt * 64 + hh*2 + 1] + bmix[hh*2 + 1];
        float mx = fmaxf(a0, a1);
        float e0 = expf(a0 - mx), e1 = expf(a1 - mx);
        float rinv = 1.f / (e0 + e1);
        size_t base = (((size_t)b * NH_ + hh) * M_) * T_ + t;
        mixo[base]      = e0 * rinv;
        mixo[base + T_] = e1 * rinv;
    }
}

// ---------------- sequential scan: warp per (b,h,m), lane owns column c of S ----------------
__global__ __launch_bounds__(64) void scan_kernel(
    const float* __restrict__ phiq, const float* __restrict__ phik,
    const float* __restrict__ vt,   const float* __restrict__ beta,
    const float* __restrict__ mix,  float* __restrict__ ypart)
{
    const int bh   = blockIdx.x;
    const int m    = threadIdx.y;
    const int lane = threadIdx.x;
    const int b = bh >> 5, h = bh & 31;

    const size_t vecbase = (size_t)bh * T_ * D_;
    const size_t bmbase  = ((size_t)bh * M_ + m) * T_;
    const size_t ybase   = (size_t)m * (B_*T_*H_) + (size_t)b * T_ * H_ + (size_t)h * D_ + lane;

    float S[32];
#pragma unroll
    for (int d = 0; d < 32; d++) S[d] = 0.f;
    float Kst = 0.f;

    for (int t = 0; t < T_; t++) {
        float pq = phiq[vecbase + (size_t)t * D_ + lane];
        float pk = phik[vecbase + (size_t)t * D_ + lane];
        float vc = vt  [vecbase + (size_t)t * D_ + lane];
        float bt = beta[bmbase + t];
        float mt = mix [bmbase + t];

        Kst = fmaf(Kst, bt, pk);
        float den = pq * Kst;
#pragma unroll
        for (int o = 16; o > 0; o >>= 1)
            den += __shfl_xor_sync(0xffffffffu, den, o);
        den += 1e-6f;

        float num0 = 0.f, num1 = 0.f, num2 = 0.f, num3 = 0.f;
#pragma unroll
        for (int d = 0; d < 32; d += 4) {
            float kd0 = __shfl_sync(0xffffffffu, pk, d);
            float qd0 = __shfl_sync(0xffffffffu, pq, d);
            S[d] = fmaf(S[d], bt, kd0 * vc);
            num0 = fmaf(qd0, S[d], num0);
            float kd1 = __shfl_sync(0xffffffffu, pk, d + 1);
            float qd1 = __shfl_sync(0xffffffffu, pq, d + 1);
            S[d + 1] = fmaf(S[d + 1], bt, kd1 * vc);
            num1 = fmaf(qd1, S[d + 1], num1);
            float kd2 = __shfl_sync(0xffffffffu, pk, d + 2);
            float qd2 = __shfl_sync(0xffffffffu, pq, d + 2);
            S[d + 2] = fmaf(S[d + 2], bt, kd2 * vc);
            num2 = fmaf(qd2, S[d + 2], num2);
            float kd3 = __shfl_sync(0xffffffffu, pk, d + 3);
            float qd3 = __shfl_sync(0xffffffffu, pq, d + 3);
            S[d + 3] = fmaf(S[d + 3], bt, kd3 * vc);
            num3 = fmaf(qd3, S[d + 3], num3);
        }

        ypart[ybase + (size_t)t * H_] = mt * ((num0 + num1) + (num2 + num3)) / den;
    }
}

// ---------------- LayerNorm ----------------
__global__ __launch_bounds__(256) void ln_kernel(
    const float* __restrict__ z, const float* __restrict__ gamma,
    const float* __restrict__ bta, float* __restrict__ out)
{
    const int row = blockIdx.x;
    const float* zr = z + (size_t)row * H_;
    float s = 0.f, ss = 0.f;
    for (int i = threadIdx.x; i < H_; i += 256) {
        float v = zr[i]; s += v; ss = fmaf(v, v, ss);
    }
    __shared__ float sh[64];
#pragma unroll
    for (int o = 16; o > 0; o >>= 1) {
        s  += __shfl_xor_sync(0xffffffffu, s, o);
        ss += __shfl_xor_sync(0xffffffffu, ss, o);
    }
    int wid = threadIdx.x >> 5, lane = threadIdx.x & 31;
    if (lane == 0) { sh[wid] = s; sh[32 + wid] = ss; }
    __syncthreads();
    if (threadIdx.x < 32) {
        float a = (threadIdx.x < 8) ? sh[threadIdx.x] : 0.f;
        float c = (threadIdx.x < 8) ? sh[32 + threadIdx.x] : 0.f;
#pragma unroll
        for (int o = 4; o > 0; o >>= 1) {
            a += __shfl_xor_sync(0xffffffffu, a, o);
            c += __shfl_xor_sync(0xffffffffu, c, o);
        }
        if (threadIdx.x == 0) { sh[0] = a; sh[1] = c; }
    }
    __syncthreads();
    float mu  = sh[0] * (1.f / H_);
    float var = sh[1] * (1.f / H_) - mu * mu;
    float rstd = rsqrtf(var + 1e-5f);
    for (int i = threadIdx.x; i < H_; i += 256)
        out[(size_t)row * H_ + i] = (zr[i] - mu) * rstd * gamma[i] + bta[i];
}

// ---------------- launch ----------------
extern "C" void kernel_launch(void* const* d_in, const int* in_sizes, int n_in,
                              void* d_out, int out_size)
{
    const float* x     = (const float*)d_in[0];
    const float* Wq    = (const float*)d_in[1];
    const float* Wk    = (const float*)d_in[2];
    const float* Wv    = (const float*)d_in[3];
    const float* Wbeta = (const float*)d_in[4];
    const float* bbeta = (const float*)d_in[5];
    const float* Wmix  = (const float*)d_in[6];
    const float* bmix  = (const float*)d_in[7];
    const float* Wout  = (const float*)d_in[8];
    const float* bout  = (const float*)d_in[9];
    const float* ln_g  = (const float*)d_in[10];
    const float* ln_b  = (const float*)d_in[11];
    float* out = (float*)d_out;

    float *qraw,*kraw,*vraw,*phiq,*phik,*vt,*braw,*mraw,*beta,*mix,*ypart,*ysum,*z;
    cudaGetSymbolAddress((void**)&qraw, g_qraw);
    cudaGetSymbolAddress((void**)&kraw, g_kraw);
    cudaGetSymbolAddress((void**)&vraw, g_vraw);
    cudaGetSymbolAddress((void**)&phiq, g_phiq);
    cudaGetSymbolAddress((void**)&phik, g_phik);
    cudaGetSymbolAddress((void**)&vt,   g_vt);
    cudaGetSymbolAddress((void**)&braw, g_braw);
    cudaGetSymbolAddress((void**)&mraw, g_mraw);
    cudaGetSymbolAddress((void**)&beta, g_beta);
    cudaGetSymbolAddress((void**)&mix,  g_mix);
    cudaGetSymbolAddress((void**)&ypart,g_ypart);
    cudaGetSymbolAddress((void**)&ysum, g_ysum);
    cudaGetSymbolAddress((void**)&z,    g_z);

    cudaFuncSetAttribute(gemm_mma<0>, cudaFuncAttributeMaxDynamicSharedMemorySize, GSMEM_BYTES);
    cudaFuncSetAttribute(gemm_mma<1>, cudaFuncAttributeMaxDynamicSharedMemorySize, GSMEM_BYTES);
    cudaFuncSetAttribute(gemm_mma<2>, cudaFuncAttributeMaxDynamicSharedMemorySize, GSMEM_BYTES);

    dim3 big(8, 32);

    gemm_mma<0><<<big, 256, GSMEM_BYTES>>>(x, Wq, nullptr, qraw, nullptr, nullptr, nullptr);
    gemm_mma<0><<<big, 256, GSMEM_BYTES>>>(x, Wk, nullptr, kraw, nullptr, nullptr, nullptr);
    gemm_mma<0><<<big, 256, GSMEM_BYTES>>>(x, Wv, nullptr, vraw, nullptr, nullptr, nullptr);
    gemm_mma<1><<<dim3(1, 32), 256, GSMEM_BYTES>>>(x, Wbeta, Wmix, braw, mraw, nullptr, nullptr);

    prep_kernel<<<B_*T_, 512>>>(qraw, kraw, vraw, braw, mraw, bbeta, bmix,
                                phiq, phik, vt, beta, mix);

    scan_kernel<<<B_*NH_, dim3(32, 2)>>>(phiq, phik, vt, beta, mix, ypart);

    add_kernel<<<(B_*T_*H_/4)/256, 256>>>(ypart, ypart + (size_t)B_*T_*H_, ysum);

    gemm_mma<2><<<big, 256, GSMEM_BYTES>>>(ysum, Wout, nullptr, z, nullptr, bout, x);

    ln_kernel<<<B_*T_, 256>>>(z, ln_g, ln_b, out);
}

// round 5
// speedup vs baseline: 1.0007x; 1.0007x over previous
#include <cuda_runtime.h>
#include <math.h>
#include <stdint.h>

#define B_  4
#define T_  1024
#define H_  1024
#define NH_ 32
#define D_  32
#define M_  2
#define K_  1024

// ---------------- scratch (static device globals; no allocation) ----------------
__device__ float g_qraw [B_*T_*H_];
__device__ float g_kraw [B_*T_*H_];
__device__ float g_vraw [B_*T_*H_];
__device__ float g_phiq [B_*T_*H_];   // [b,h,t,d]
__device__ float g_phik [B_*T_*H_];   // [b,h,t,d]
__device__ float g_vt   [B_*T_*H_];   // [b,h,t,d]
__device__ float g_braw [B_*T_*NH_*M_];
__device__ float g_mraw [B_*T_*NH_*M_];
__device__ float g_beta [B_*NH_*M_*T_]; // [b,h,m,t]
__device__ float g_mix  [B_*NH_*M_*T_]; // [b,h,m,t]
__device__ float g_ypart[2*B_*T_*H_];   // [m][b,t,H]
__device__ float g_ysum [B_*T_*H_];
__device__ float g_z    [B_*T_*H_];

// ==================== helpers ====================
__device__ __forceinline__ uint32_t smem_u32(const void* p) {
    uint32_t a;
    asm("{ .reg .u64 t; cvta.to.shared.u64 t, %1; cvt.u32.u64 %0, t; }" : "=r"(a) : "l"(p));
    return a;
}

__device__ __forceinline__ void cp_async16(uint32_t dst, const void* src) {
    asm volatile("cp.async.ca.shared.global [%0], [%1], 16;" :: "r"(dst), "l"(src));
}
__device__ __forceinline__ void cp_commit() { asm volatile("cp.async.commit_group;"); }
template<int N> __device__ __forceinline__ void cp_wait() {
    asm volatile("cp.async.wait_group %0;" :: "n"(N));
}

__device__ __forceinline__ uint32_t f2tf32(float x) {
    uint32_t u;
    asm("cvt.rna.tf32.f32 %0, %1;" : "=r"(u) : "f"(x));
    return u;
}

__device__ __forceinline__ void mma_tf32x(float* c, const uint32_t* a, const uint32_t* b) {
    asm volatile("mma.sync.aligned.m16n8k8.row.col.f32.tf32.tf32.f32 "
        "{%0,%1,%2,%3}, {%4,%5,%6,%7}, {%8,%9}, {%0,%1,%2,%3};"
        : "+f"(c[0]), "+f"(c[1]), "+f"(c[2]), "+f"(c[3])
        : "r"(a[0]), "r"(a[1]), "r"(a[2]), "r"(a[3]), "r"(b[0]), "r"(b[1]));
}

// ==================== tf32x3 mma.sync GEMM ====================
// C[M,N] = A[M,K] . B[N,K]^T. CTA tile 128x128, KC=32 double-buffered via cp.async.
// 8 warps: warp tile 64x32 (wm = wid/4, wn = wid%4).
// MODE 0: plain (QKV). MODE 1: beta/mix fused (B rows 0-63 Wbeta, 64-127 Wmix;
//   out cols 0-63 -> C, 64-127 -> C2, both [row][64]). MODE 2: epilogue + bias + xres.

#define S_WORDS 12
#define SLICE_FL (128*S_WORDS)       // floats per k8-slice (128 rows x 12 words)
#define BUF_FL   (4*SLICE_FL)        // 4 slices = KC 32
#define A_FL     (2*BUF_FL)
#define GSMEM_BYTES (4*BUF_FL*4)     // A(2 buf) + B(2 buf) = 98304 B

template<int MODE>
__global__ void __launch_bounds__(256) gemm_mma(
    const float* __restrict__ A, const float* __restrict__ Bw1, const float* __restrict__ Bw2,
    float* __restrict__ C, float* __restrict__ C2,
    const float* __restrict__ bias, const float* __restrict__ xres)
{
    extern __shared__ float sm[];
    float* As = sm;                 // [2 buf][4 slice][128 row][12 words]
    float* Bs = sm + A_FL;

    const int tid  = threadIdx.x;
    const int row0 = blockIdx.y * 128;
    const int col0 = blockIdx.x * 128;
    const int lane = tid & 31;
    const int wm = ((tid >> 7) & 1) * 64;   // (wid>>2)*64
    const int wn = ((tid >> 5) & 3) * 32;   // (wid&3)*32

    // cp.async sources: thread covers row=tid/2, k-half = (tid&1)*16
    const int ldrow = tid >> 1;
    const int kh    = (tid & 1) * 16;
    const float* asrc = A + (size_t)(row0 + ldrow) * K_ + kh;
    const float* bsrc;
    if (MODE == 1) bsrc = ((ldrow < 64) ? Bw1 + (size_t)ldrow * K_
                                        : Bw2 + (size_t)(ldrow - 64) * K_) + kh;
    else           bsrc = Bw1 + (size_t)(col0 + ldrow) * K_ + kh;

    const uint32_t sa = smem_u32(sm);
    uint32_t offA[4];
#pragma unroll
    for (int q = 0; q < 4; q++) {
        int k = kh + q * 4;
        int s = k >> 3, w = k & 7;
        offA[q] = (uint32_t)(((s * 128 + ldrow) * S_WORDS + w) * 4);
    }

#define ISSUE(chunk, buf) do { \
    const float* _ap = asrc + (chunk) * 32; \
    const float* _bp = bsrc + (chunk) * 32; \
    uint32_t _b = sa + (uint32_t)(buf) * (BUF_FL * 4); \
    _Pragma("unroll") \
    for (int q = 0; q < 4; q++) { \
        cp_async16(_b + offA[q], _ap + q * 4); \
        cp_async16(_b + (uint32_t)(A_FL * 4) + offA[q], _bp + q * 4); \
    } \
    cp_commit(); } while (0)

    ISSUE(0, 0);
    ISSUE(1, 1);

    float cc[64];
#pragma unroll
    for (int x = 0; x < 64; x++) cc[x] = 0.f;

#define MMALOOP(AA, BB) do { \
    _Pragma("unroll") \
    for (int mt = 0; mt < 4; mt++) \
    _Pragma("unroll") \
    for (int nt = 0; nt < 4; nt++) \
        mma_tf32x(&cc[(mt*4+nt)*4], &(AA)[mt*4], &(BB)[nt*2]); } while (0)

    for (int i = 0; i < 32; i++) {
        if (i < 30) cp_wait<1>(); else cp_wait<0>();
        __syncthreads();
        const int buf = i & 1;
        const float* Ab = As + buf * BUF_FL;
        const float* Bb = Bs + buf * BUF_FL;

        for (int s = 0; s < 4; s++) {
            const float* Asl = Ab + s * SLICE_FL;
            const float* Bsl = Bb + s * SLICE_FL;
            float af[16], bf[8];
#pragma unroll
            for (int mt = 0; mt < 4; mt++) {
                int base = (wm + mt * 16 + (lane >> 2)) * S_WORDS + (lane & 3);
                af[mt*4+0] = Asl[base];
                af[mt*4+1] = Asl[base + 8 * S_WORDS];
                af[mt*4+2] = Asl[base + 4];
                af[mt*4+3] = Asl[base + 8 * S_WORDS + 4];
            }
#pragma unroll
            for (int nt = 0; nt < 4; nt++) {
                int base = (wn + nt * 8 + (lane >> 2)) * S_WORDS + (lane & 3);
                bf[nt*2+0] = Bsl[base];
                bf[nt*2+1] = Bsl[base + 4];
            }
            uint32_t ah[16], bh[8];
#pragma unroll
            for (int x = 0; x < 16; x++) ah[x] = f2tf32(af[x]);
#pragma unroll
            for (int x = 0; x < 8;  x++) bh[x] = f2tf32(bf[x]);
            MMALOOP(ah, bh);                       // hi * hi
            {
                uint32_t al[16];
#pragma unroll
                for (int x = 0; x < 16; x++) al[x] = f2tf32(af[x] - __uint_as_float(ah[x]));
                MMALOOP(al, bh);                   // lo_a * hi_b
            }
            {
                uint32_t bl[8];
#pragma unroll
                for (int x = 0; x < 8; x++) bl[x] = f2tf32(bf[x] - __uint_as_float(bh[x]));
                MMALOOP(ah, bl);                   // hi_a * lo_b
            }
        }
        __syncthreads();
        if (i + 2 < 32) ISSUE(i + 2, buf);
    }

    // ---- epilogue ----
#pragma unroll
    for (int mt = 0; mt < 4; mt++)
#pragma unroll
    for (int nt = 0; nt < 4; nt++) {
        const int r = row0 + wm + mt * 16 + (lane >> 2);
        const int c = col0 + wn + nt * 8 + (lane & 3) * 2;
        float* p = &cc[(mt*4+nt)*4];
        if (MODE == 0) {
            *(float2*)&C[(size_t)r * H_ + c]       = make_float2(p[0], p[1]);
            *(float2*)&C[(size_t)(r+8) * H_ + c]   = make_float2(p[2], p[3]);
        } else if (MODE == 1) {
            float* d0;
            float* d1;
            if (c < 64) { d0 = &C [(size_t)r * 64 + c];      d1 = &C [(size_t)(r+8) * 64 + c]; }
            else        { d0 = &C2[(size_t)r * 64 + c - 64]; d1 = &C2[(size_t)(r+8) * 64 + c - 64]; }
            *(float2*)d0 = make_float2(p[0], p[1]);
            *(float2*)d1 = make_float2(p[2], p[3]);
        } else {
            const size_t o0 = (size_t)r * H_ + c, o1 = (size_t)(r+8) * H_ + c;
            float2 x0 = *(const float2*)&xres[o0];
            float2 x1 = *(const float2*)&xres[o1];
            float2 bb = *(const float2*)&bias[c];
            *(float2*)&C[o0] = make_float2(p[0] + bb.x + x0.x, p[1] + bb.y + x0.y);
            *(float2*)&C[o1] = make_float2(p[2] + bb.x + x1.x, p[3] + bb.y + x1.y);
        }
    }
#undef ISSUE
#undef MMALOOP
}

// ---------------- ysum = ypart[0] + ypart[1] ----------------
__global__ __launch_bounds__(256) void add_kernel(
    const float* __restrict__ a, const float* __restrict__ b, float* __restrict__ o)
{
    int i = blockIdx.x * 256 + threadIdx.x;
    float4 va = ((const float4*)a)[i];
    float4 vb = ((const float4*)b)[i];
    ((float4*)o)[i] = make_float4(va.x + vb.x, va.y + vb.y, va.z + vb.z, va.w + vb.w);
}

// ---------------- preprocess: RoPE + phi, sigmoid/clip beta, softmax mix, transpose v ----------------
__global__ __launch_bounds__(512) void prep_kernel(
    const float* __restrict__ qraw, const float* __restrict__ kraw,
    const float* __restrict__ vraw, const float* __restrict__ braw,
    const float* __restrict__ mraw, const float* __restrict__ bbeta,
    const float* __restrict__ bmix,
    float* __restrict__ phiq, float* __restrict__ phik, float* __restrict__ vt,
    float* __restrict__ beta, float* __restrict__ mixo)
{
    const int bt = blockIdx.x;           // 0..4095
    const int b  = bt >> 10;
    const int t  = bt & 1023;
    const int tid = threadIdx.x;         // 0..511
    const int h  = tid >> 4;             // 0..31
    const int i  = tid & 15;             // 0..15

    float inv = expf(-(float)i * (0.0625f * 9.210340371976184f)); // 10000^(-i/16)
    float ang = (float)t * inv;
    float s = sinf(ang), c = cosf(ang);

    size_t src = (size_t)bt * H_ + (size_t)h * 32;
    float q1 = qraw[src + i], q2 = qraw[src + 16 + i];
    float k1 = kraw[src + i], k2 = kraw[src + 16 + i];
    float rq1 = q1*c - q2*s, rq2 = q1*s + q2*c;
    float rk1 = k1*c - k2*s, rk2 = k1*s + k2*c;

    size_t dst = (((size_t)b * NH_ + h) * T_ + t) * D_;
    phiq[dst + i]      = (rq1 > 0.f) ? rq1 + 1.f : expf(rq1);
    phiq[dst + 16 + i] = (rq2 > 0.f) ? rq2 + 1.f : expf(rq2);
    phik[dst + i]      = (rk1 > 0.f) ? rk1 + 1.f : expf(rk1);
    phik[dst + 16 + i] = (rk2 > 0.f) ? rk2 + 1.f : expf(rk2);

    {
        int e  = tid * 2;
        int hh = e >> 5, dd = e & 31;
        float2 vv = *(const float2*)(vraw + (size_t)bt * H_ + e);
        size_t vd = (((size_t)b * NH_ + hh) * T_ + t) * D_ + dd;
        *(float2*)(vt + vd) = vv;
    }

    if (tid < 64) {
        float xv = braw[(size_t)bt * 64 + tid] + bbeta[tid];
        float sg = 1.f / (1.f + expf(-xv));
        sg = fminf(fmaxf(sg, 0.85f), 0.9995f);
        int hh = tid >> 1, mm = tid & 1;
        beta[(((size_t)b * NH_ + hh) * M_ + mm) * T_ + t] = sg;
    }
    if (tid < 32) {
        int hh = tid;
        float a0 = mraw[(size_t)bt * 64 + hh*2]     + bmix[hh*2];
        float a1 = mraw[(size_t)bt * 64 + hh*2 + 1] + bmix[hh*2 + 1];
        float mx = fmaxf(a0, a1);
        float e0 = expf(a0 - mx), e1 = expf(a1 - mx);
        float rinv = 1.f / (e0 + e1);
        size_t base = (((size_t)b * NH_ + hh) * M_) * T_ + t;
        mixo[base]      = e0 * rinv;
        mixo[base + T_] = e1 * rinv;
    }
}

// ---------------- sequential scan: warp per (b,h,m), lane owns column c of S ----------------
__global__ __launch_bounds__(64) void scan_kernel(
    const float* __restrict__ phiq, const float* __restrict__ phik,
    const float* __restrict__ vt,   const float* __restrict__ beta,
    const float* __restrict__ mix,  float* __restrict__ ypart)
{
    const int bh   = blockIdx.x;
    const int m    = threadIdx.y;
    const int lane = threadIdx.x;
    const int b = bh >> 5, h = bh & 31;

    const size_t vecbase = (size_t)bh * T_ * D_;
    const size_t bmbase  = ((size_t)bh * M_ + m) * T_;
    const size_t ybase   = (size_t)m * (B_*T_*H_) + (size_t)b * T_ * H_ + (size_t)h * D_ + lane;

    float S[32];
#pragma unroll
    for (int d = 0; d < 32; d++) S[d] = 0.f;
    float Kst = 0.f;

    for (int t = 0; t < T_; t++) {
        float pq = phiq[vecbase + (size_t)t * D_ + lane];
        float pk = phik[vecbase + (size_t)t * D_ + lane];
        float vc = vt  [vecbase + (size_t)t * D_ + lane];
        float bt = beta[bmbase + t];
        float mt = mix [bmbase + t];

        Kst = fmaf(Kst, bt, pk);
        float den = pq * Kst;
#pragma unroll
        for (int o = 16; o > 0; o >>= 1)
            den += __shfl_xor_sync(0xffffffffu, den, o);
        den += 1e-6f;

        float num0 = 0.f, num1 = 0.f, num2 = 0.f, num3 = 0.f;
#pragma unroll
        for (int d = 0; d < 32; d += 4) {
            float kd0 = __shfl_sync(0xffffffffu, pk, d);
            float qd0 = __shfl_sync(0xffffffffu, pq, d);
            S[d] = fmaf(S[d], bt, kd0 * vc);
            num0 = fmaf(qd0, S[d], num0);
            float kd1 = __shfl_sync(0xffffffffu, pk, d + 1);
            float qd1 = __shfl_sync(0xffffffffu, pq, d + 1);
            S[d + 1] = fmaf(S[d + 1], bt, kd1 * vc);
            num1 = fmaf(qd1, S[d + 1], num1);
            float kd2 = __shfl_sync(0xffffffffu, pk, d + 2);
            float qd2 = __shfl_sync(0xffffffffu, pq, d + 2);
            S[d + 2] = fmaf(S[d + 2], bt, kd2 * vc);
            num2 = fmaf(qd2, S[d + 2], num2);
            float kd3 = __shfl_sync(0xffffffffu, pk, d + 3);
            float qd3 = __shfl_sync(0xffffffffu, pq, d + 3);
            S[d + 3] = fmaf(S[d + 3], bt, kd3 * vc);
            num3 = fmaf(qd3, S[d + 3], num3);
        }

        ypart[ybase + (size_t)t * H_] = mt * ((num0 + num1) + (num2 + num3)) / den;
    }
}

// ---------------- LayerNorm ----------------
__global__ __launch_bounds__(256) void ln_kernel(
    const float* __restrict__ z, const float* __restrict__ gamma,
    const float* __restrict__ bta, float* __restrict__ out)
{
    const int row = blockIdx.x;
    const float* zr = z + (size_t)row * H_;
    float s = 0.f, ss = 0.f;
    for (int i = threadIdx.x; i < H_; i += 256) {
        float v = zr[i]; s += v; ss = fmaf(v, v, ss);
    }
    __shared__ float sh[64];
#pragma unroll
    for (int o = 16; o > 0; o >>= 1) {
        s  += __shfl_xor_sync(0xffffffffu, s, o);
        ss += __shfl_xor_sync(0xffffffffu, ss, o);
    }
    int wid = threadIdx.x >> 5, lane = threadIdx.x & 31;
    if (lane == 0) { sh[wid] = s; sh[32 + wid] = ss; }
    __syncthreads();
    if (threadIdx.x < 32) {
        float a = (threadIdx.x < 8) ? sh[threadIdx.x] : 0.f;
        float c = (threadIdx.x < 8) ? sh[32 + threadIdx.x] : 0.f;
#pragma unroll
        for (int o = 4; o > 0; o >>= 1) {
            a += __shfl_xor_sync(0xffffffffu, a, o);
            c += __shfl_xor_sync(0xffffffffu, c, o);
        }
        if (threadIdx.x == 0) { sh[0] = a; sh[1] = c; }
    }
    __syncthreads();
    float mu  = sh[0] * (1.f / H_);
    float var = sh[1] * (1.f / H_) - mu * mu;
    float rstd = rsqrtf(var + 1e-5f);
    for (int i = threadIdx.x; i < H_; i += 256)
        out[(size_t)row * H_ + i] = (zr[i] - mu) * rstd * gamma[i] + bta[i];
}

// ---------------- launch ----------------
extern "C" void kernel_launch(void* const* d_in, const int* in_sizes, int n_in,
                              void* d_out, int out_size)
{
    const float* x     = (const float*)d_in[0];
    const float* Wq    = (const float*)d_in[1];
    const float* Wk    = (const float*)d_in[2];
    const float* Wv    = (const float*)d_in[3];
    const float* Wbeta = (const float*)d_in[4];
    const float* bbeta = (const float*)d_in[5];
    const float* Wmix  = (const float*)d_in[6];
    const float* bmix  = (const float*)d_in[7];
    const float* Wout  = (const float*)d_in[8];
    const float* bout  = (const float*)d_in[9];
    const float* ln_g  = (const float*)d_in[10];
    const float* ln_b  = (const float*)d_in[11];
    float* out = (float*)d_out;

    float *qraw,*kraw,*vraw,*phiq,*phik,*vt,*braw,*mraw,*beta,*mix,*ypart,*ysum,*z;
    cudaGetSymbolAddress((void**)&qraw, g_qraw);
    cudaGetSymbolAddress((void**)&kraw, g_kraw);
    cudaGetSymbolAddress((void**)&vraw, g_vraw);
    cudaGetSymbolAddress((void**)&phiq, g_phiq);
    cudaGetSymbolAddress((void**)&phik, g_phik);
    cudaGetSymbolAddress((void**)&vt,   g_vt);
    cudaGetSymbolAddress((void**)&braw, g_braw);
    cudaGetSymbolAddress((void**)&mraw, g_mraw);
    cudaGetSymbolAddress((void**)&beta, g_beta);
    cudaGetSymbolAddress((void**)&mix,  g_mix);
    cudaGetSymbolAddress((void**)&ypart,g_ypart);
    cudaGetSymbolAddress((void**)&ysum, g_ysum);
    cudaGetSymbolAddress((void**)&z,    g_z);

    cudaFuncSetAttribute(gemm_mma<0>, cudaFuncAttributeMaxDynamicSharedMemorySize, GSMEM_BYTES);
    cudaFuncSetAttribute(gemm_mma<1>, cudaFuncAttributeMaxDynamicSharedMemorySize, GSMEM_BYTES);
    cudaFuncSetAttribute(gemm_mma<2>, cudaFuncAttributeMaxDynamicSharedMemorySize, GSMEM_BYTES);

    dim3 big(8, 32);

    gemm_mma<0><<<big, 256, GSMEM_BYTES>>>(x, Wq, nullptr, qraw, nullptr, nullptr, nullptr);
    gemm_mma<0><<<big, 256, GSMEM_BYTES>>>(x, Wk, nullptr, kraw, nullptr, nullptr, nullptr);
    gemm_mma<0><<<big, 256, GSMEM_BYTES>>>(x, Wv, nullptr, vraw, nullptr, nullptr, nullptr);
    gemm_mma<1><<<dim3(1, 32), 256, GSMEM_BYTES>>>(x, Wbeta, Wmix, braw, mraw, nullptr, nullptr);

    prep_kernel<<<B_*T_, 512>>>(qraw, kraw, vraw, braw, mraw, bbeta, bmix,
                                phiq, phik, vt, beta, mix);

    scan_kernel<<<B_*NH_, dim3(32, 2)>>>(phiq, phik, vt, beta, mix, ypart);

    add_kernel<<<(B_*T_*H_/4)/256, 256>>>(ypart, ypart + (size_t)B_*T_*H_, ysum);

    gemm_mma<2><<<big, 256, GSMEM_BYTES>>>(ysum, Wout, nullptr, z, nullptr, bout, x);

    ln_kernel<<<B_*T_, 256>>>(z, ln_g, ln_b, out);
}

// round 6
// speedup vs baseline: 1.0010x; 1.0003x over previous
#include <cuda_runtime.h>
#include <math.h>
#include <stdint.h>

#define B_  4
#define T_  1024
#define H_  1024
#define NH_ 32
#define D_  32
#define M_  2
#define K_  1024

// ---------------- scratch (static device globals; no allocation) ----------------
__device__ float g_qraw [B_*T_*H_];
__device__ float g_kraw [B_*T_*H_];
__device__ float g_vraw [B_*T_*H_];
__device__ float g_phiq [B_*T_*H_];   // [b,h,t,d]
__device__ float g_phik [B_*T_*H_];   // [b,h,t,d]
__device__ float g_vt   [B_*T_*H_];   // [b,h,t,d]
__device__ float g_braw [B_*T_*NH_*M_];
__device__ float g_mraw [B_*T_*NH_*M_];
__device__ float g_beta [B_*NH_*M_*T_]; // [b,h,m,t]
__device__ float g_mix  [B_*NH_*M_*T_]; // [b,h,m,t]
__device__ float g_ypart[2*B_*T_*H_];   // [m][b,t,H]
__device__ float g_ysum [B_*T_*H_];
__device__ float g_z    [B_*T_*H_];

// ==================== helpers ====================
__device__ __forceinline__ uint32_t smem_u32(const void* p) {
    uint32_t a;
    asm("{ .reg .u64 t; cvta.to.shared.u64 t, %1; cvt.u32.u64 %0, t; }" : "=r"(a) : "l"(p));
    return a;
}

__device__ __forceinline__ void cp_async16(uint32_t dst, const void* src) {
    asm volatile("cp.async.ca.shared.global [%0], [%1], 16;" :: "r"(dst), "l"(src));
}
__device__ __forceinline__ void cp_commit() { asm volatile("cp.async.commit_group;"); }
template<int N> __device__ __forceinline__ void cp_wait() {
    asm volatile("cp.async.wait_group %0;" :: "n"(N));
}

__device__ __forceinline__ uint32_t f2tf32(float x) {
    uint32_t u;
    asm("cvt.rna.tf32.f32 %0, %1;" : "=r"(u) : "f"(x));
    return u;
}

__device__ __forceinline__ void mma_tf32x(float* c, const uint32_t* a, const uint32_t* b) {
    asm volatile("mma.sync.aligned.m16n8k8.row.col.f32.tf32.tf32.f32 "
        "{%0,%1,%2,%3}, {%4,%5,%6,%7}, {%8,%9}, {%0,%1,%2,%3};"
        : "+f"(c[0]), "+f"(c[1]), "+f"(c[2]), "+f"(c[3])
        : "r"(a[0]), "r"(a[1]), "r"(a[2]), "r"(a[3]), "r"(b[0]), "r"(b[1]));
}

// ==================== tf32x3 mma.sync GEMM ====================
// C[M,N] = A[M,K] . B[N,K]^T. CTA tile 128x128, KC=32 double-buffered via cp.async.
// 8 warps: warp tile 64x32 (wm = wid/4, wn = wid%4).
// MODE 0: plain (QKV). MODE 1: beta/mix fused (B rows 0-63 Wbeta, 64-127 Wmix;
//   out cols 0-63 -> C, 64-127 -> C2, both [row][64]). MODE 2: epilogue + bias + xres.

#define S_WORDS 12
#define SLICE_FL (128*S_WORDS)       // floats per k8-slice (128 rows x 12 words)
#define BUF_FL   (4*SLICE_FL)        // 4 slices = KC 32
#define A_FL     (2*BUF_FL)
#define GSMEM_BYTES (4*BUF_FL*4)     // A(2 buf) + B(2 buf) = 98304 B

template<int MODE>
__global__ void __launch_bounds__(256) gemm_mma(
    const float* __restrict__ A, const float* __restrict__ Bw1, const float* __restrict__ Bw2,
    float* __restrict__ C, float* __restrict__ C2,
    const float* __restrict__ bias, const float* __restrict__ xres)
{
    extern __shared__ float sm[];
    float* As = sm;                 // [2 buf][4 slice][128 row][12 words]
    float* Bs = sm + A_FL;

    const int tid  = threadIdx.x;
    const int row0 = blockIdx.y * 128;
    const int col0 = blockIdx.x * 128;
    const int lane = tid & 31;
    const int wm = ((tid >> 7) & 1) * 64;   // (wid>>2)*64
    const int wn = ((tid >> 5) & 3) * 32;   // (wid&3)*32

    // cp.async sources: thread covers row=tid/2, k-half = (tid&1)*16
    const int ldrow = tid >> 1;
    const int kh    = (tid & 1) * 16;
    const float* asrc = A + (size_t)(row0 + ldrow) * K_ + kh;
    const float* bsrc;
    if (MODE == 1) bsrc = ((ldrow < 64) ? Bw1 + (size_t)ldrow * K_
                                        : Bw2 + (size_t)(ldrow - 64) * K_) + kh;
    else           bsrc = Bw1 + (size_t)(col0 + ldrow) * K_ + kh;

    const uint32_t sa = smem_u32(sm);
    uint32_t offA[4];
#pragma unroll
    for (int q = 0; q < 4; q++) {
        int k = kh + q * 4;
        int s = k >> 3, w = k & 7;
        offA[q] = (uint32_t)(((s * 128 + ldrow) * S_WORDS + w) * 4);
    }

#define ISSUE(chunk, buf) do { \
    const float* _ap = asrc + (chunk) * 32; \
    const float* _bp = bsrc + (chunk) * 32; \
    uint32_t _b = sa + (uint32_t)(buf) * (BUF_FL * 4); \
    _Pragma("unroll") \
    for (int q = 0; q < 4; q++) { \
        cp_async16(_b + offA[q], _ap + q * 4); \
        cp_async16(_b + (uint32_t)(A_FL * 4) + offA[q], _bp + q * 4); \
    } \
    cp_commit(); } while (0)

    ISSUE(0, 0);
    ISSUE(1, 1);

    float cc[64];
#pragma unroll
    for (int x = 0; x < 64; x++) cc[x] = 0.f;

#define MMALOOP(AA, BB) do { \
    _Pragma("unroll") \
    for (int mt = 0; mt < 4; mt++) \
    _Pragma("unroll") \
    for (int nt = 0; nt < 4; nt++) \
        mma_tf32x(&cc[(mt*4+nt)*4], &(AA)[mt*4], &(BB)[nt*2]); } while (0)

    for (int i = 0; i < 32; i++) {
        if (i < 30) cp_wait<1>(); else cp_wait<0>();
        __syncthreads();
        const int buf = i & 1;
        const float* Ab = As + buf * BUF_FL;
        const float* Bb = Bs + buf * BUF_FL;

        for (int s = 0; s < 4; s++) {
            const float* Asl = Ab + s * SLICE_FL;
            const float* Bsl = Bb + s * SLICE_FL;
            float af[16], bf[8];
#pragma unroll
            for (int mt = 0; mt < 4; mt++) {
                int base = (wm + mt * 16 + (lane >> 2)) * S_WORDS + (lane & 3);
                af[mt*4+0] = Asl[base];
                af[mt*4+1] = Asl[base + 8 * S_WORDS];
                af[mt*4+2] = Asl[base + 4];
                af[mt*4+3] = Asl[base + 8 * S_WORDS + 4];
            }
#pragma unroll
            for (int nt = 0; nt < 4; nt++) {
                int base = (wn + nt * 8 + (lane >> 2)) * S_WORDS + (lane & 3);
                bf[nt*2+0] = Bsl[base];
                bf[nt*2+1] = Bsl[base + 4];
            }
            uint32_t ah[16], bh[8];
#pragma unroll
            for (int x = 0; x < 16; x++) ah[x] = f2tf32(af[x]);
#pragma unroll
            for (int x = 0; x < 8;  x++) bh[x] = f2tf32(bf[x]);
            MMALOOP(ah, bh);                       // hi * hi
            {
                uint32_t al[16];
#pragma unroll
                for (int x = 0; x < 16; x++) al[x] = f2tf32(af[x] - __uint_as_float(ah[x]));
                MMALOOP(al, bh);                   // lo_a * hi_b
            }
            {
                uint32_t bl[8];
#pragma unroll
                for (int x = 0; x < 8; x++) bl[x] = f2tf32(bf[x] - __uint_as_float(bh[x]));
                MMALOOP(ah, bl);                   // hi_a * lo_b
            }
        }
        __syncthreads();
        if (i + 2 < 32) ISSUE(i + 2, buf);
    }

    // ---- epilogue ----
#pragma unroll
    for (int mt = 0; mt < 4; mt++)
#pragma unroll
    for (int nt = 0; nt < 4; nt++) {
        const int r = row0 + wm + mt * 16 + (lane >> 2);
        const int c = col0 + wn + nt * 8 + (lane & 3) * 2;
        float* p = &cc[(mt*4+nt)*4];
        if (MODE == 0) {
            *(float2*)&C[(size_t)r * H_ + c]       = make_float2(p[0], p[1]);
            *(float2*)&C[(size_t)(r+8) * H_ + c]   = make_float2(p[2], p[3]);
        } else if (MODE == 1) {
            float* d0;
            float* d1;
            if (c < 64) { d0 = &C [(size_t)r * 64 + c];      d1 = &C [(size_t)(r+8) * 64 + c]; }
            else        { d0 = &C2[(size_t)r * 64 + c - 64]; d1 = &C2[(size_t)(r+8) * 64 + c - 64]; }
            *(float2*)d0 = make_float2(p[0], p[1]);
            *(float2*)d1 = make_float2(p[2], p[3]);
        } else {
            const size_t o0 = (size_t)r * H_ + c, o1 = (size_t)(r+8) * H_ + c;
            float2 x0 = *(const float2*)&xres[o0];
            float2 x1 = *(const float2*)&xres[o1];
            float2 bb = *(const float2*)&bias[c];
            *(float2*)&C[o0] = make_float2(p[0] + bb.x + x0.x, p[1] + bb.y + x0.y);
            *(float2*)&C[o1] = make_float2(p[2] + bb.x + x1.x, p[3] + bb.y + x1.y);
        }
    }
#undef ISSUE
#undef MMALOOP
}

// ---------------- ysum = ypart[0] + ypart[1] ----------------
__global__ __launch_bounds__(256) void add_kernel(
    const float* __restrict__ a, const float* __restrict__ b, float* __restrict__ o)
{
    int i = blockIdx.x * 256 + threadIdx.x;
    float4 va = ((const float4*)a)[i];
    float4 vb = ((const float4*)b)[i];
    ((float4*)o)[i] = make_float4(va.x + vb.x, va.y + vb.y, va.z + vb.z, va.w + vb.w);
}

// ---------------- preprocess: RoPE + phi, sigmoid/clip beta, softmax mix, transpose v ----------------
__global__ __launch_bounds__(512) void prep_kernel(
    const float* __restrict__ qraw, const float* __restrict__ kraw,
    const float* __restrict__ vraw, const float* __restrict__ braw,
    const float* __restrict__ mraw, const float* __restrict__ bbeta,
    const float* __restrict__ bmix,
    float* __restrict__ phiq, float* __restrict__ phik, float* __restrict__ vt,
    float* __restrict__ beta, float* __restrict__ mixo)
{
    const int bt = blockIdx.x;           // 0..4095
    const int b  = bt >> 10;
    const int t  = bt & 1023;
    const int tid = threadIdx.x;         // 0..511
    const int h  = tid >> 4;             // 0..31
    const int i  = tid & 15;             // 0..15

    float inv = expf(-(float)i * (0.0625f * 9.210340371976184f)); // 10000^(-i/16)
    float ang = (float)t * inv;
    float s = sinf(ang), c = cosf(ang);

    size_t src = (size_t)bt * H_ + (size_t)h * 32;
    float q1 = qraw[src + i], q2 = qraw[src + 16 + i];
    float k1 = kraw[src + i], k2 = kraw[src + 16 + i];
    float rq1 = q1*c - q2*s, rq2 = q1*s + q2*c;
    float rk1 = k1*c - k2*s, rk2 = k1*s + k2*c;

    size_t dst = (((size_t)b * NH_ + h) * T_ + t) * D_;
    phiq[dst + i]      = (rq1 > 0.f) ? rq1 + 1.f : expf(rq1);
    phiq[dst + 16 + i] = (rq2 > 0.f) ? rq2 + 1.f : expf(rq2);
    phik[dst + i]      = (rk1 > 0.f) ? rk1 + 1.f : expf(rk1);
    phik[dst + 16 + i] = (rk2 > 0.f) ? rk2 + 1.f : expf(rk2);

    {
        int e  = tid * 2;
        int hh = e >> 5, dd = e & 31;
        float2 vv = *(const float2*)(vraw + (size_t)bt * H_ + e);
        size_t vd = (((size_t)b * NH_ + hh) * T_ + t) * D_ + dd;
        *(float2*)(vt + vd) = vv;
    }

    if (tid < 64) {
        float xv = braw[(size_t)bt * 64 + tid] + bbeta[tid];
        float sg = 1.f / (1.f + expf(-xv));
        sg = fminf(fmaxf(sg, 0.85f), 0.9995f);
        int hh = tid >> 1, mm = tid & 1;
        beta[(((size_t)b * NH_ + hh) * M_ + mm) * T_ + t] = sg;
    }
    if (tid < 32) {
        int hh = tid;
        float a0 = mraw[(size_t)bt * 64 + hh*2]     + bmix[hh*2];
        float a1 = mraw[(size_t)bt * 64 + hh*2 + 1] + bmix[hh*2 + 1];
        float mx = fmaxf(a0, a1);
        float e0 = expf(a0 - mx), e1 = expf(a1 - mx);
        float rinv = 1.f / (e0 + e1);
        size_t base = (((size_t)b * NH_ + hh) * M_) * T_ + t;
        mixo[base]      = e0 * rinv;
        mixo[base + T_] = e1 * rinv;
    }
}

// ---------------- sequential scan: warp per (b,h,m), lane owns column c of S ----------------
__global__ __launch_bounds__(64) void scan_kernel(
    const float* __restrict__ phiq, const float* __restrict__ phik,
    const float* __restrict__ vt,   const float* __restrict__ beta,
    const float* __restrict__ mix,  float* __restrict__ ypart)
{
    const int bh   = blockIdx.x;
    const int m    = threadIdx.y;
    const int lane = threadIdx.x;
    const int b = bh >> 5, h = bh & 31;

    const size_t vecbase = (size_t)bh * T_ * D_;
    const size_t bmbase  = ((size_t)bh * M_ + m) * T_;
    const size_t ybase   = (size_t)m * (B_*T_*H_) + (size_t)b * T_ * H_ + (size_t)h * D_ + lane;

    float S[32];
#pragma unroll
    for (int d = 0; d < 32; d++) S[d] = 0.f;
    float Kst = 0.f;

    for (int t = 0; t < T_; t++) {
        float pq = phiq[vecbase + (size_t)t * D_ + lane];
        float pk = phik[vecbase + (size_t)t * D_ + lane];
        float vc = vt  [vecbase + (size_t)t * D_ + lane];
        float bt = beta[bmbase + t];
        float mt = mix [bmbase + t];

        Kst = fmaf(Kst, bt, pk);
        float den = pq * Kst;
#pragma unroll
        for (int o = 16; o > 0; o >>= 1)
            den += __shfl_xor_sync(0xffffffffu, den, o);
        den += 1e-6f;

        float num0 = 0.f, num1 = 0.f, num2 = 0.f, num3 = 0.f;
#pragma unroll
        for (int d = 0; d < 32; d += 4) {
            float kd0 = __shfl_sync(0xffffffffu, pk, d);
            float qd0 = __shfl_sync(0xffffffffu, pq, d);
            S[d] = fmaf(S[d], bt, kd0 * vc);
            num0 = fmaf(qd0, S[d], num0);
            float kd1 = __shfl_sync(0xffffffffu, pk, d + 1);
            float qd1 = __shfl_sync(0xffffffffu, pq, d + 1);
            S[d + 1] = fmaf(S[d + 1], bt, kd1 * vc);
            num1 = fmaf(qd1, S[d + 1], num1);
            float kd2 = __shfl_sync(0xffffffffu, pk, d + 2);
            float qd2 = __shfl_sync(0xffffffffu, pq, d + 2);
            S[d + 2] = fmaf(S[d + 2], bt, kd2 * vc);
            num2 = fmaf(qd2, S[d + 2], num2);
            float kd3 = __shfl_sync(0xffffffffu, pk, d + 3);
            float qd3 = __shfl_sync(0xffffffffu, pq, d + 3);
            S[d + 3] = fmaf(S[d + 3], bt, kd3 * vc);
            num3 = fmaf(qd3, S[d + 3], num3);
        }

        ypart[ybase + (size_t)t * H_] = mt * ((num0 + num1) + (num2 + num3)) / den;
    }
}

// ---------------- LayerNorm ----------------
__global__ __launch_bounds__(256) void ln_kernel(
    const float* __restrict__ z, const float* __restrict__ gamma,
    const float* __restrict__ bta, float* __restrict__ out)
{
    const int row = blockIdx.x;
    const float* zr = z + (size_t)row * H_;
    float s = 0.f, ss = 0.f;
    for (int i = threadIdx.x; i < H_; i += 256) {
        float v = zr[i]; s += v; ss = fmaf(v, v, ss);
    }
    __shared__ float sh[64];
#pragma unroll
    for (int o = 16; o > 0; o >>= 1) {
        s  += __shfl_xor_sync(0xffffffffu, s, o);
        ss += __shfl_xor_sync(0xffffffffu, ss, o);
    }
    int wid = threadIdx.x >> 5, lane = threadIdx.x & 31;
    if (lane == 0) { sh[wid] = s; sh[32 + wid] = ss; }
    __syncthreads();
    if (threadIdx.x < 32) {
        float a = (threadIdx.x < 8) ? sh[threadIdx.x] : 0.f;
        float c = (threadIdx.x < 8) ? sh[32 + threadIdx.x] : 0.f;
#pragma unroll
        for (int o = 4; o > 0; o >>= 1) {
            a += __shfl_xor_sync(0xffffffffu, a, o);
            c += __shfl_xor_sync(0xffffffffu, c, o);
        }
        if (threadIdx.x == 0) { sh[0] = a; sh[1] = c; }
    }
    __syncthreads();
    float mu  = sh[0] * (1.f / H_);
    float var = sh[1] * (1.f / H_) - mu * mu;
    float rstd = rsqrtf(var + 1e-5f);
    for (int i = threadIdx.x; i < H_; i += 256)
        out[(size_t)row * H_ + i] = (zr[i] - mu) * rstd * gamma[i] + bta[i];
}

// ---------------- launch ----------------
extern "C" void kernel_launch(void* const* d_in, const int* in_sizes, int n_in,
                              void* d_out, int out_size)
{
    const float* x     = (const float*)d_in[0];
    const float* Wq    = (const float*)d_in[1];
    const float* Wk    = (const float*)d_in[2];
    const float* Wv    = (const float*)d_in[3];
    const float* Wbeta = (const float*)d_in[4];
    const float* bbeta = (const float*)d_in[5];
    const float* Wmix  = (const float*)d_in[6];
    const float* bmix  = (const float*)d_in[7];
    const float* Wout  = (const float*)d_in[8];
    const float* bout  = (const float*)d_in[9];
    const float* ln_g  = (const float*)d_in[10];
    const float* ln_b  = (const float*)d_in[11];
    float* out = (float*)d_out;

    float *qraw,*kraw,*vraw,*phiq,*phik,*vt,*braw,*mraw,*beta,*mix,*ypart,*ysum,*z;
    cudaGetSymbolAddress((void**)&qraw, g_qraw);
    cudaGetSymbolAddress((void**)&kraw, g_kraw);
    cudaGetSymbolAddress((void**)&vraw, g_vraw);
    cudaGetSymbolAddress((void**)&phiq, g_phiq);
    cudaGetSymbolAddress((void**)&phik, g_phik);
    cudaGetSymbolAddress((void**)&vt,   g_vt);
    cudaGetSymbolAddress((void**)&braw, g_braw);
    cudaGetSymbolAddress((void**)&mraw, g_mraw);
    cudaGetSymbolAddress((void**)&beta, g_beta);
    cudaGetSymbolAddress((void**)&mix,  g_mix);
    cudaGetSymbolAddress((void**)&ypart,g_ypart);
    cudaGetSymbolAddress((void**)&ysum, g_ysum);
    cudaGetSymbolAddress((void**)&z,    g_z);

    cudaFuncSetAttribute(gemm_mma<0>, cudaFuncAttributeMaxDynamicSharedMemorySize, GSMEM_BYTES);
    cudaFuncSetAttribute(gemm_mma<1>, cudaFuncAttributeMaxDynamicSharedMemorySize, GSMEM_BYTES);
    cudaFuncSetAttribute(gemm_mma<2>, cudaFuncAttributeMaxDynamicSharedMemorySize, GSMEM_BYTES);

    dim3 big(8, 32);

    gemm_mma<0><<<big, 256, GSMEM_BYTES>>>(x, Wq, nullptr, qraw, nullptr, nullptr, nullptr);
    gemm_mma<0><<<big, 256, GSMEM_BYTES>>>(x, Wk, nullptr, kraw, nullptr, nullptr, nullptr);
    gemm_mma<0><<<big, 256, GSMEM_BYTES>>>(x, Wv, nullptr, vraw, nullptr, nullptr, nullptr);
    gemm_mma<1><<<dim3(1, 32), 256, GSMEM_BYTES>>>(x, Wbeta, Wmix, braw, mraw, nullptr, nullptr);

    prep_kernel<<<B_*T_, 512>>>(qraw, kraw, vraw, braw, mraw, bbeta, bmix,
                                phiq, phik, vt, beta, mix);

    scan_kernel<<<B_*NH_, dim3(32, 2)>>>(phiq, phik, vt, beta, mix, ypart);

    add_kernel<<<(B_*T_*H_/4)/256, 256>>>(ypart, ypart + (size_t)B_*T_*H_, ysum);

    gemm_mma<2><<<big, 256, GSMEM_BYTES>>>(ysum, Wout, nullptr, z, nullptr, bout, x);

    ln_kernel<<<B_*T_, 256>>>(z, ln_g, ln_b, out);
}

// round 7
// speedup vs baseline: 1.9668x; 1.9648x over previous
#include <cuda_runtime.h>
#include <math.h>
#include <stdint.h>

#define B_  4
#define T_  1024
#define H_  1024
#define NH_ 32
#define D_  32
#define M_  2
#define K_  1024
#define NC_ 32           // chunks of 32 timesteps
#define BHM_ (B_*NH_*M_)

// ---------------- scratch ----------------
__device__ float g_qraw [B_*T_*H_];
__device__ float g_kraw [B_*T_*H_];
__device__ float g_vraw [B_*T_*H_];
__device__ float g_phiq [B_*T_*H_];   // [b,h,t,d]
__device__ float g_phik [B_*T_*H_];   // [b,h,t,d]
__device__ float g_vt   [B_*T_*H_];   // [b,h,t,d]
__device__ float g_braw [B_*T_*NH_*M_];
__device__ float g_mraw [B_*T_*NH_*M_];
__device__ float g_beta [BHM_*T_];    // [b,h,m,t]
__device__ float g_mix  [BHM_*T_];    // [b,h,m,t]
__device__ float g_P    [BHM_*T_];    // chunk-local cumprod of beta
__device__ float g_U    [(size_t)BHM_*NC_*1024]; // per-chunk K~^T V, [bhm][c][e][d]
__device__ float g_ksum [BHM_*NC_*32];
__device__ float g_Scar [(size_t)BHM_*NC_*1024]; // carry S entering chunk, [e][d]
__device__ float g_Kcar [BHM_*NC_*32];
__device__ float g_ysum [B_*T_*H_];
__device__ float g_z    [B_*T_*H_];

// ==================== helpers ====================
__device__ __forceinline__ uint32_t smem_u32(const void* p) {
    uint32_t a;
    asm("{ .reg .u64 t; cvta.to.shared.u64 t, %1; cvt.u32.u64 %0, t; }" : "=r"(a) : "l"(p));
    return a;
}
__device__ __forceinline__ void cp_async16(uint32_t dst, const void* src) {
    asm volatile("cp.async.ca.shared.global [%0], [%1], 16;" :: "r"(dst), "l"(src));
}
__device__ __forceinline__ void cp_commit() { asm volatile("cp.async.commit_group;"); }
template<int N> __device__ __forceinline__ void cp_wait() {
    asm volatile("cp.async.wait_group %0;" :: "n"(N));
}
__device__ __forceinline__ uint32_t f2tf32(float x) {
    uint32_t u;
    asm("cvt.rna.tf32.f32 %0, %1;" : "=r"(u) : "f"(x));
    return u;
}
__device__ __forceinline__ void mma_tf32x(float* c, const uint32_t* a, const uint32_t* b) {
    asm volatile("mma.sync.aligned.m16n8k8.row.col.f32.tf32.tf32.f32 "
        "{%0,%1,%2,%3}, {%4,%5,%6,%7}, {%8,%9}, {%0,%1,%2,%3};"
        : "+f"(c[0]), "+f"(c[1]), "+f"(c[2]), "+f"(c[3])
        : "r"(a[0]), "r"(a[1]), "r"(a[2]), "r"(a[3]), "r"(b[0]), "r"(b[1]));
}

// ==================== tf32x3 mma.sync GEMM ====================
// C[M,N] = A[M,K].B[N,K]^T. CTA 128x128, KC=16, 3-stage cp.async pipeline, 2 CTAs/SM.
// MODE 0: plain. MODE 1: beta/mix fused. MODE 2: epilogue + bias + residual.

#define KC 16
#define NCH 64
#define S_WORDS 12
#define SLICE_FL (128*S_WORDS)       // 1536 floats per k8-slice
#define STG_FL (2*SLICE_FL)          // 3072 floats per matrix per stage
#define A_FL (3*STG_FL)              // 3 stages
#define GSMEM_BYTES (2*A_FL*4)       // 73728 B

template<int MODE>
__global__ void __launch_bounds__(256, 2) gemm_mma(
    const float* __restrict__ A, const float* __restrict__ Bw1, const float* __restrict__ Bw2,
    float* __restrict__ C, float* __restrict__ C2,
    const float* __restrict__ bias, const float* __restrict__ xres)
{
    extern __shared__ float sm[];
    float* As = sm;
    float* Bs = sm + A_FL;

    const int tid  = threadIdx.x;
    const int row0 = blockIdx.y * 128;
    const int col0 = blockIdx.x * 128;
    const int lane = tid & 31;
    const int wm = ((tid >> 7) & 1) * 64;
    const int wn = ((tid >> 5) & 3) * 32;

    const int ldrow = tid >> 1;
    const int half  = tid & 1;              // k-half of 16: 8 floats each
    const float* asrc = A + (size_t)(row0 + ldrow) * K_ + half * 8;
    const float* bsrc;
    if (MODE == 1) bsrc = ((ldrow < 64) ? Bw1 + (size_t)ldrow * K_
                                        : Bw2 + (size_t)(ldrow - 64) * K_) + half * 8;
    else           bsrc = Bw1 + (size_t)(col0 + ldrow) * K_ + half * 8;

    const uint32_t sa = smem_u32(sm);
    uint32_t offs[2];
#pragma unroll
    for (int q = 0; q < 2; q++)
        offs[q] = (uint32_t)((((half * 128 + ldrow) * S_WORDS) + q * 4) * 4);

#define ISSUE(chunk, stg) do { \
    const float* _ap = asrc + (chunk) * KC; \
    const float* _bp = bsrc + (chunk) * KC; \
    uint32_t _b = sa + (uint32_t)(stg) * (STG_FL * 4); \
    cp_async16(_b + offs[0], _ap); \
    cp_async16(_b + offs[1], _ap + 4); \
    cp_async16(_b + (uint32_t)(A_FL * 4) + offs[0], _bp); \
    cp_async16(_b + (uint32_t)(A_FL * 4) + offs[1], _bp + 4); \
    cp_commit(); } while (0)

    ISSUE(0, 0); ISSUE(1, 1); ISSUE(2, 2);

    float cc[64];
#pragma unroll
    for (int x = 0; x < 64; x++) cc[x] = 0.f;

#define MMALOOP(AA, BB) do { \
    _Pragma("unroll") \
    for (int mt = 0; mt < 4; mt++) \
    _Pragma("unroll") \
    for (int nt = 0; nt < 4; nt++) \
        mma_tf32x(&cc[(mt*4+nt)*4], &(AA)[mt*4], &(BB)[nt*2]); } while (0)

    int stg = 0;
    for (int i = 0; i < NCH; i++) {
        if (i <= NCH - 3)      cp_wait<2>();
        else if (i == NCH - 2) cp_wait<1>();
        else                   cp_wait<0>();
        __syncthreads();
        const float* Ab = As + stg * STG_FL;
        const float* Bb = Bs + stg * STG_FL;

#pragma unroll
        for (int s = 0; s < 2; s++) {
            const float* Asl = Ab + s * SLICE_FL;
            const float* Bsl = Bb + s * SLICE_FL;
            float af[16], bf[8];
#pragma unroll
            for (int mt = 0; mt < 4; mt++) {
                int base = (wm + mt * 16 + (lane >> 2)) * S_WORDS + (lane & 3);
                af[mt*4+0] = Asl[base];
                af[mt*4+1] = Asl[base + 8 * S_WORDS];
                af[mt*4+2] = Asl[base + 4];
                af[mt*4+3] = Asl[base + 8 * S_WORDS + 4];
            }
#pragma unroll
            for (int nt = 0; nt < 4; nt++) {
                int base = (wn + nt * 8 + (lane >> 2)) * S_WORDS + (lane & 3);
                bf[nt*2+0] = Bsl[base];
                bf[nt*2+1] = Bsl[base + 4];
            }
            uint32_t ah[16], bh[8];
#pragma unroll
            for (int x = 0; x < 16; x++) ah[x] = f2tf32(af[x]);
#pragma unroll
            for (int x = 0; x < 8;  x++) bh[x] = f2tf32(bf[x]);
            MMALOOP(ah, bh);
            {
                uint32_t al[16];
#pragma unroll
                for (int x = 0; x < 16; x++) al[x] = f2tf32(af[x] - __uint_as_float(ah[x]));
                MMALOOP(al, bh);
            }
            {
                uint32_t bl[8];
#pragma unroll
                for (int x = 0; x < 8; x++) bl[x] = f2tf32(bf[x] - __uint_as_float(bh[x]));
                MMALOOP(ah, bl);
            }
        }
        __syncthreads();
        if (i + 3 < NCH) ISSUE(i + 3, stg);
        stg = (stg == 2) ? 0 : stg + 1;
    }

    // ---- epilogue ----
#pragma unroll
    for (int mt = 0; mt < 4; mt++)
#pragma unroll
    for (int nt = 0; nt < 4; nt++) {
        const int r = row0 + wm + mt * 16 + (lane >> 2);
        const int c = col0 + wn + nt * 8 + (lane & 3) * 2;
        float* p = &cc[(mt*4+nt)*4];
        if (MODE == 0) {
            *(float2*)&C[(size_t)r * H_ + c]     = make_float2(p[0], p[1]);
            *(float2*)&C[(size_t)(r+8) * H_ + c] = make_float2(p[2], p[3]);
        } else if (MODE == 1) {
            float* d0; float* d1;
            if (c < 64) { d0 = &C [(size_t)r * 64 + c];      d1 = &C [(size_t)(r+8) * 64 + c]; }
            else        { d0 = &C2[(size_t)r * 64 + c - 64]; d1 = &C2[(size_t)(r+8) * 64 + c - 64]; }
            *(float2*)d0 = make_float2(p[0], p[1]);
            *(float2*)d1 = make_float2(p[2], p[3]);
        } else {
            const size_t o0 = (size_t)r * H_ + c, o1 = (size_t)(r+8) * H_ + c;
            float2 x0 = *(const float2*)&xres[o0];
            float2 x1 = *(const float2*)&xres[o1];
            float2 bb = *(const float2*)&bias[c];
            *(float2*)&C[o0] = make_float2(p[0] + bb.x + x0.x, p[1] + bb.y + x0.y);
            *(float2*)&C[o1] = make_float2(p[2] + bb.x + x1.x, p[3] + bb.y + x1.y);
        }
    }
#undef ISSUE
#undef MMALOOP
}

// ---------------- prep: RoPE + phi, beta, mix, v transpose ----------------
__global__ __launch_bounds__(512) void prep_kernel(
    const float* __restrict__ qraw, const float* __restrict__ kraw,
    const float* __restrict__ vraw, const float* __restrict__ braw,
    const float* __restrict__ mraw, const float* __restrict__ bbeta,
    const float* __restrict__ bmix,
    float* __restrict__ phiq, float* __restrict__ phik, float* __restrict__ vt,
    float* __restrict__ beta, float* __restrict__ mixo)
{
    const int bt = blockIdx.x;
    const int b  = bt >> 10;
    const int t  = bt & 1023;
    const int tid = threadIdx.x;
    const int h  = tid >> 4;
    const int i  = tid & 15;

    float inv = expf(-(float)i * (0.0625f * 9.210340371976184f));
    float ang = (float)t * inv;
    float s = sinf(ang), c = cosf(ang);

    size_t src = (size_t)bt * H_ + (size_t)h * 32;
    float q1 = qraw[src + i], q2 = qraw[src + 16 + i];
    float k1 = kraw[src + i], k2 = kraw[src + 16 + i];
    float rq1 = q1*c - q2*s, rq2 = q1*s + q2*c;
    float rk1 = k1*c - k2*s, rk2 = k1*s + k2*c;

    size_t dst = (((size_t)b * NH_ + h) * T_ + t) * D_;
    phiq[dst + i]      = (rq1 > 0.f) ? rq1 + 1.f : expf(rq1);
    phiq[dst + 16 + i] = (rq2 > 0.f) ? rq2 + 1.f : expf(rq2);
    phik[dst + i]      = (rk1 > 0.f) ? rk1 + 1.f : expf(rk1);
    phik[dst + 16 + i] = (rk2 > 0.f) ? rk2 + 1.f : expf(rk2);

    {
        int e  = tid * 2;
        int hh = e >> 5, dd = e & 31;
        float2 vv = *(const float2*)(vraw + (size_t)bt * H_ + e);
        size_t vd = (((size_t)b * NH_ + hh) * T_ + t) * D_ + dd;
        *(float2*)(vt + vd) = vv;
    }

    if (tid < 64) {
        float xv = braw[(size_t)bt * 64 + tid] + bbeta[tid];
        float sg = 1.f / (1.f + expf(-xv));
        sg = fminf(fmaxf(sg, 0.85f), 0.9995f);
        int hh = tid >> 1, mm = tid & 1;
        beta[(((size_t)b * NH_ + hh) * M_ + mm) * T_ + t] = sg;
    }
    if (tid < 32) {
        int hh = tid;
        float a0 = mraw[(size_t)bt * 64 + hh*2]     + bmix[hh*2];
        float a1 = mraw[(size_t)bt * 64 + hh*2 + 1] + bmix[hh*2 + 1];
        float mx = fmaxf(a0, a1);
        float e0 = expf(a0 - mx), e1 = expf(a1 - mx);
        float rinv = 1.f / (e0 + e1);
        size_t base = (((size_t)b * NH_ + hh) * M_) * T_ + t;
        mixo[base]      = e0 * rinv;
        mixo[base + T_] = e1 * rinv;
    }
}

// ---------------- chunk-local cumprod of beta ----------------
__global__ __launch_bounds__(32) void cumprod_kernel(
    const float* __restrict__ beta, float* __restrict__ P)
{
    const int blk = blockIdx.x;         // bhm*NC + c
    const int bhm = blk >> 5, c = blk & 31;
    const int lane = threadIdx.x;
    size_t idx = (size_t)bhm * T_ + c * 32 + lane;
    float v = beta[idx];
#pragma unroll
    for (int o = 1; o < 32; o <<= 1) {
        float u = __shfl_up_sync(0xffffffffu, v, o);
        if (lane >= o) v *= u;
    }
    P[idx] = v;
}

// ---------------- per-chunk U = K~^T V (stored [e][d]) and ksum ----------------
__global__ __launch_bounds__(256) void chunk_sum_kernel(
    const float* __restrict__ phik, const float* __restrict__ vt,
    const float* __restrict__ P, float* __restrict__ U, float* __restrict__ ksum)
{
    const int blk = blockIdx.x;         // bhm*NC + c
    const int bhm = blk >> 5, c = blk & 31;
    const int bh  = bhm >> 1;
    const int t0  = c * 32;

    __shared__ float kt[32][33];
    __shared__ float vv[32][33];

    const int tl = threadIdx.x >> 3;
    const int x4 = (threadIdx.x & 7) * 4;

    float Pt  = P[(size_t)bhm * T_ + t0 + tl];
    float inv = 1.f / Pt;
    size_t base = ((size_t)bh * T_ + t0 + tl) * 32 + x4;
    float4 kv = *(const float4*)(phik + base);
    kt[tl][x4+0] = kv.x * inv; kt[tl][x4+1] = kv.y * inv;
    kt[tl][x4+2] = kv.z * inv; kt[tl][x4+3] = kv.w * inv;
    float4 vz = *(const float4*)(vt + base);
    vv[tl][x4+0] = vz.x; vv[tl][x4+1] = vz.y; vv[tl][x4+2] = vz.z; vv[tl][x4+3] = vz.w;
    __syncthreads();

    const int e = tl;
    float a0 = 0.f, a1 = 0.f, a2 = 0.f, a3 = 0.f;
#pragma unroll
    for (int t = 0; t < 32; t++) {
        float ve = vv[t][e];
        a0 = fmaf(kt[t][x4+0], ve, a0);
        a1 = fmaf(kt[t][x4+1], ve, a1);
        a2 = fmaf(kt[t][x4+2], ve, a2);
        a3 = fmaf(kt[t][x4+3], ve, a3);
    }
    *(float4*)(U + (size_t)blk * 1024 + e * 32 + x4) = make_float4(a0, a1, a2, a3);

    if (threadIdx.x < 32) {
        int d = threadIdx.x;
        float s = 0.f;
#pragma unroll
        for (int t = 0; t < 32; t++) s += kt[t][d];
        ksum[(size_t)blk * 32 + d] = s;
    }
}

// ---------------- sequential carry over chunks (1 warp per bhm) ----------------
__global__ __launch_bounds__(32) void carry_kernel(
    const float* __restrict__ P, const float* __restrict__ U,
    const float* __restrict__ ksum, float* __restrict__ Scar, float* __restrict__ Kcar)
{
    const int bhm = blockIdx.x;
    const int e = threadIdx.x;
    float S[32];
#pragma unroll
    for (int d = 0; d < 32; d++) S[d] = 0.f;
    float Kv = 0.f;

    for (int c = 0; c < NC_; c++) {
        size_t tb = (size_t)bhm * NC_ + c;
        float* sd = Scar + tb * 1024 + e * 32;
#pragma unroll
        for (int q = 0; q < 8; q++)
            ((float4*)sd)[q] = make_float4(S[4*q], S[4*q+1], S[4*q+2], S[4*q+3]);
        Kcar[tb * 32 + e] = Kv;

        float PL = P[(size_t)bhm * T_ + c * 32 + 31];
        const float* ud = U + tb * 1024 + e * 32;
#pragma unroll
        for (int q = 0; q < 8; q++) {
            float4 u = ((const float4*)ud)[q];
            S[4*q+0] = PL * (S[4*q+0] + u.x);
            S[4*q+1] = PL * (S[4*q+1] + u.y);
            S[4*q+2] = PL * (S[4*q+2] + u.z);
            S[4*q+3] = PL * (S[4*q+3] + u.w);
        }
        Kv = PL * (Kv + ksum[tb * 32 + e]);
    }
}

// ---------------- per-chunk output: y = mix * (tril(Q~K~^T)V + Q~ S0) / den ----------------
__global__ __launch_bounds__(256) void chunk_out_kernel(
    const float* __restrict__ phiq, const float* __restrict__ phik,
    const float* __restrict__ vt,   const float* __restrict__ P,
    const float* __restrict__ mix,  const float* __restrict__ Scar,
    const float* __restrict__ Kcar, float* __restrict__ y)
{
    const int blk = blockIdx.x;         // bh*NC + c
    const int bh = blk >> 5, c = blk & 31;
    const int t0 = c * 32;

    __shared__ float qt[32][33];
    __shared__ float kt[32][33];
    __shared__ float vv[32][33];
    __shared__ float ST[32][33];
    __shared__ float A [32][33];
    __shared__ float den[32];
    __shared__ float K0[32];

    const int tid = threadIdx.x;
    const int tl = tid >> 3;
    const int x4 = (tid & 7) * 4;
    const int lane = tid & 31, w = tid >> 5;

    size_t vbase = ((size_t)bh * T_ + t0 + tl) * 32 + x4;
    {
        float4 vz = *(const float4*)(vt + vbase);
        vv[tl][x4+0] = vz.x; vv[tl][x4+1] = vz.y; vv[tl][x4+2] = vz.z; vv[tl][x4+3] = vz.w;
    }

    float yac[4] = {0.f, 0.f, 0.f, 0.f};

    for (int m = 0; m < 2; m++) {
        const int bhm = bh * 2 + m;
        float Pt  = P[(size_t)bhm * T_ + t0 + tl];
        float inv = 1.f / Pt;
        float4 qv = *(const float4*)(phiq + vbase);
        float4 kv = *(const float4*)(phik + vbase);
        qt[tl][x4+0] = qv.x * Pt;  qt[tl][x4+1] = qv.y * Pt;
        qt[tl][x4+2] = qv.z * Pt;  qt[tl][x4+3] = qv.w * Pt;
        kt[tl][x4+0] = kv.x * inv; kt[tl][x4+1] = kv.y * inv;
        kt[tl][x4+2] = kv.z * inv; kt[tl][x4+3] = kv.w * inv;

        size_t tb = (size_t)bhm * NC_ + c;
        float4 sv = ((const float4*)(Scar + tb * 1024))[tid];
        ST[tl][x4+0] = sv.x; ST[tl][x4+1] = sv.y; ST[tl][x4+2] = sv.z; ST[tl][x4+3] = sv.w;
        if (tid < 32) K0[tid] = Kcar[tb * 32 + tid];
        __syncthreads();

        // A[t][j] = q~_t . k~_j (masked j<=t)
        float a[4] = {0.f, 0.f, 0.f, 0.f};
#pragma unroll
        for (int d = 0; d < 32; d++) {
            float qd = qt[tl][d];
            a[0] = fmaf(qd, kt[x4+0][d], a[0]);
            a[1] = fmaf(qd, kt[x4+1][d], a[1]);
            a[2] = fmaf(qd, kt[x4+2][d], a[2]);
            a[3] = fmaf(qd, kt[x4+3][d], a[3]);
        }
#pragma unroll
        for (int q = 0; q < 4; q++)
            A[tl][x4+q] = (x4 + q <= tl) ? a[q] : 0.f;
        __syncthreads();

        // den[t] = sum_j A[t][j] + q~_t . K0 + eps (full row sum: masked zeros)
#pragma unroll
        for (int r = 0; r < 4; r++) {
            int t = w * 4 + r;
            float v = A[t][lane] + qt[t][lane] * K0[lane];
#pragma unroll
            for (int o = 16; o > 0; o >>= 1)
                v += __shfl_xor_sync(0xffffffffu, v, o);
            if (lane == 0) den[t] = v + 1e-6f;
        }
        __syncthreads();

        float mixv = mix[(size_t)bhm * T_ + t0 + tl];
        float f = mixv / den[tl];
        float n[4] = {0.f, 0.f, 0.f, 0.f};
#pragma unroll
        for (int j = 0; j < 32; j++) {
            float aj = A[tl][j];
            n[0] = fmaf(aj, vv[j][x4+0], n[0]);
            n[1] = fmaf(aj, vv[j][x4+1], n[1]);
            n[2] = fmaf(aj, vv[j][x4+2], n[2]);
            n[3] = fmaf(aj, vv[j][x4+3], n[3]);
        }
#pragma unroll
        for (int d = 0; d < 32; d++) {
            float qd = qt[tl][d];
            n[0] = fmaf(qd, ST[x4+0][d], n[0]);
            n[1] = fmaf(qd, ST[x4+1][d], n[1]);
            n[2] = fmaf(qd, ST[x4+2][d], n[2]);
            n[3] = fmaf(qd, ST[x4+3][d], n[3]);
        }
#pragma unroll
        for (int q = 0; q < 4; q++) yac[q] = fmaf(f, n[q], yac[q]);
        __syncthreads();
    }

    const int b = bh >> 5, h = bh & 31;
    *(float4*)(y + ((size_t)(b * T_ + t0 + tl)) * H_ + h * 32 + x4)
        = make_float4(yac[0], yac[1], yac[2], yac[3]);
}

// ---------------- LayerNorm ----------------
__global__ __launch_bounds__(256) void ln_kernel(
    const float* __restrict__ z, const float* __restrict__ gamma,
    const float* __restrict__ bta, float* __restrict__ out)
{
    const int row = blockIdx.x;
    const float* zr = z + (size_t)row * H_;
    float s = 0.f, ss = 0.f;
    for (int i = threadIdx.x; i < H_; i += 256) {
        float v = zr[i]; s += v; ss = fmaf(v, v, ss);
    }
    __shared__ float sh[64];
#pragma unroll
    for (int o = 16; o > 0; o >>= 1) {
        s  += __shfl_xor_sync(0xffffffffu, s, o);
        ss += __shfl_xor_sync(0xffffffffu, ss, o);
    }
    int wid = threadIdx.x >> 5, lane = threadIdx.x & 31;
    if (lane == 0) { sh[wid] = s; sh[32 + wid] = ss; }
    __syncthreads();
    if (threadIdx.x < 32) {
        float a = (threadIdx.x < 8) ? sh[threadIdx.x] : 0.f;
        float c = (threadIdx.x < 8) ? sh[32 + threadIdx.x] : 0.f;
#pragma unroll
        for (int o = 4; o > 0; o >>= 1) {
            a += __shfl_xor_sync(0xffffffffu, a, o);
            c += __shfl_xor_sync(0xffffffffu, c, o);
        }
        if (threadIdx.x == 0) { sh[0] = a; sh[1] = c; }
    }
    __syncthreads();
    float mu  = sh[0] * (1.f / H_);
    float var = sh[1] * (1.f / H_) - mu * mu;
    float rstd = rsqrtf(var + 1e-5f);
    for (int i = threadIdx.x; i < H_; i += 256)
        out[(size_t)row * H_ + i] = (zr[i] - mu) * rstd * gamma[i] + bta[i];
}

// ---------------- launch ----------------
extern "C" void kernel_launch(void* const* d_in, const int* in_sizes, int n_in,
                              void* d_out, int out_size)
{
    const float* x     = (const float*)d_in[0];
    const float* Wq    = (const float*)d_in[1];
    const float* Wk    = (const float*)d_in[2];
    const float* Wv    = (const float*)d_in[3];
    const float* Wbeta = (const float*)d_in[4];
    const float* bbeta = (const float*)d_in[5];
    const float* Wmix  = (const float*)d_in[6];
    const float* bmix  = (const float*)d_in[7];
    const float* Wout  = (const float*)d_in[8];
    const float* bout  = (const float*)d_in[9];
    const float* ln_g  = (const float*)d_in[10];
    const float* ln_b  = (const float*)d_in[11];
    float* out = (float*)d_out;

    float *qraw,*kraw,*vraw,*phiq,*phik,*vt,*braw,*mraw,*beta,*mix;
    float *P,*U,*ksum,*Scar,*Kcar,*ysum,*z;
    cudaGetSymbolAddress((void**)&qraw, g_qraw);
    cudaGetSymbolAddress((void**)&kraw, g_kraw);
    cudaGetSymbolAddress((void**)&vraw, g_vraw);
    cudaGetSymbolAddress((void**)&phiq, g_phiq);
    cudaGetSymbolAddress((void**)&phik, g_phik);
    cudaGetSymbolAddress((void**)&vt,   g_vt);
    cudaGetSymbolAddress((void**)&braw, g_braw);
    cudaGetSymbolAddress((void**)&mraw, g_mraw);
    cudaGetSymbolAddress((void**)&beta, g_beta);
    cudaGetSymbolAddress((void**)&mix,  g_mix);
    cudaGetSymbolAddress((void**)&P,    g_P);
    cudaGetSymbolAddress((void**)&U,    g_U);
    cudaGetSymbolAddress((void**)&ksum, g_ksum);
    cudaGetSymbolAddress((void**)&Scar, g_Scar);
    cudaGetSymbolAddress((void**)&Kcar, g_Kcar);
    cudaGetSymbolAddress((void**)&ysum, g_ysum);
    cudaGetSymbolAddress((void**)&z,    g_z);

    cudaFuncSetAttribute(gemm_mma<0>, cudaFuncAttributeMaxDynamicSharedMemorySize, GSMEM_BYTES);
    cudaFuncSetAttribute(gemm_mma<1>, cudaFuncAttributeMaxDynamicSharedMemorySize, GSMEM_BYTES);
    cudaFuncSetAttribute(gemm_mma<2>, cudaFuncAttributeMaxDynamicSharedMemorySize, GSMEM_BYTES);

    dim3 big(8, 32);

    gemm_mma<0><<<big, 256, GSMEM_BYTES>>>(x, Wq, nullptr, qraw, nullptr, nullptr, nullptr);
    gemm_mma<0><<<big, 256, GSMEM_BYTES>>>(x, Wk, nullptr, kraw, nullptr, nullptr, nullptr);
    gemm_mma<0><<<big, 256, GSMEM_BYTES>>>(x, Wv, nullptr, vraw, nullptr, nullptr, nullptr);
    gemm_mma<1><<<dim3(1, 32), 256, GSMEM_BYTES>>>(x, Wbeta, Wmix, braw, mraw, nullptr, nullptr);

    prep_kernel<<<B_*T_, 512>>>(qraw, kraw, vraw, braw, mraw, bbeta, bmix,
                                phiq, phik, vt, beta, mix);

    cumprod_kernel<<<BHM_*NC_, 32>>>(beta, P);
    chunk_sum_kernel<<<BHM_*NC_, 256>>>(phik, vt, P, U, ksum);
    carry_kernel<<<BHM_, 32>>>(P, U, ksum, Scar, Kcar);
    chunk_out_kernel<<<B_*NH_*NC_, 256>>>(phiq, phik, vt, P, mix, Scar, Kcar, ysum);

    gemm_mma<2><<<big, 256, GSMEM_BYTES>>>(ysum, Wout, nullptr, z, nullptr, bout, x);

    ln_kernel<<<B_*T_, 256>>>(z, ln_g, ln_b, out);
}